// round 1
// baseline (speedup 1.0000x reference)
#include <cuda_runtime.h>
#include <cstdint>
#include <cstddef>

#define NN 50000
#define NE 500000
#define CH 128
#define NLAYERS 4
#define HSTEP 0.1f
#define TVEPS 1e-3f

// ---------------- scratch (device globals; no allocations allowed) ----------
__device__ float g_Xn[NN * CH];           // node activations, row-major [n][c]
__device__ float g_Yn[NN * CH];           // KN[l] @ xn, row-major
__device__ float g_D [NN * CH];           // edge_div(xe), row-major
__device__ float g_T [NN * CH];           // relu(KE[l] @ D), row-major
__device__ float g_Xe[(size_t)NE * CH];   // edge activations, row-major [e][c] (256 MB)
__device__ int   g_cnt[NN];
__device__ int   g_rowptr[NN + 1];
__device__ int   g_cur[NN];
__device__ int   g_inc[2 * NE];           // incidence list; idx<NE => +, else e=idx-NE => -
__device__ float g_sum[CH];
__device__ float g_sumsq[CH];
__device__ float g_mean[CH];
__device__ float g_inv[CH];

// ---------------- GEMM: Out[m,c] = sum_k W[c,k] * A(k,m) , K=N=128 ----------
// A_CM  : A is channel-major  A[k*M + m]   (harness input layout)
//         else A is row-major A[m*128 + k] (our scratch layout)
// OUT_CM: Out is channel-major Out[c*M + m] (final output layout)
//         else row-major Out[m*128 + c]
#define GEMM_SMEM ((CH * CH + 32 * 132) * 4)

template <bool A_CM, bool OUT_CM, bool RELU>
__global__ __launch_bounds__(256) void gemm128(const float* __restrict__ A,
                                               const float* __restrict__ W,
                                               float* __restrict__ Out, int M) {
    extern __shared__ float sm[];
    float(*Ws)[CH]  = reinterpret_cast<float(*)[CH]>(sm);         // Ws[k][c] = W[c][k]
    float(*As)[132] = reinterpret_cast<float(*)[132]>(sm + CH * CH);

    const int tid = threadIdx.x;
    const int m0  = blockIdx.x * 128;
    const int tc  = (tid & 15) * 8;
    const int tm  = (tid >> 4) * 8;

    for (int i = tid; i < CH * CH; i += 256) {
        int c = i >> 7, k = i & 127;
        Ws[k][c] = W[i];
    }

    float acc[8][8];
#pragma unroll
    for (int i = 0; i < 8; i++)
#pragma unroll
        for (int j = 0; j < 8; j++) acc[i][j] = 0.f;

    for (int k0 = 0; k0 < CH; k0 += 32) {
        __syncthreads();
        if (A_CM) {
#pragma unroll
            for (int i = tid; i < 32 * 128; i += 256) {
                int kk = i >> 7, m = i & 127;
                int gm = m0 + m;
                As[kk][m] = (gm < M) ? A[(size_t)(k0 + kk) * M + gm] : 0.f;
            }
        } else {
            int m  = tid >> 1;
            int gm = m0 + m;
            const float4* src = reinterpret_cast<const float4*>(A + (size_t)gm * CH + k0);
#pragma unroll
            for (int j = 0; j < 4; j++) {
                int q = (tid & 1) * 4 + j;
                float4 v = make_float4(0.f, 0.f, 0.f, 0.f);
                if (gm < M) v = src[q];
                As[q * 4 + 0][m] = v.x;
                As[q * 4 + 1][m] = v.y;
                As[q * 4 + 2][m] = v.z;
                As[q * 4 + 3][m] = v.w;
            }
        }
        __syncthreads();
#pragma unroll
        for (int kk = 0; kk < 32; kk++) {
            float a[8], w[8];
            *reinterpret_cast<float4*>(&a[0]) = *reinterpret_cast<const float4*>(&As[kk][tm]);
            *reinterpret_cast<float4*>(&a[4]) = *reinterpret_cast<const float4*>(&As[kk][tm + 4]);
            *reinterpret_cast<float4*>(&w[0]) = *reinterpret_cast<const float4*>(&Ws[k0 + kk][tc]);
            *reinterpret_cast<float4*>(&w[4]) = *reinterpret_cast<const float4*>(&Ws[k0 + kk][tc + 4]);
#pragma unroll
            for (int i = 0; i < 8; i++)
#pragma unroll
                for (int j = 0; j < 8; j++) acc[i][j] = fmaf(a[i], w[j], acc[i][j]);
        }
    }

    if (OUT_CM) {
#pragma unroll
        for (int j = 0; j < 8; j++) {
            int c = tc + j;
#pragma unroll
            for (int i0 = 0; i0 < 8; i0 += 4) {
                int gm = m0 + tm + i0;
                if (gm < M) {  // M % 4 == 0 and gm % 4 == 0, so full float4 in-bounds
                    float4 v;
                    v.x = acc[i0 + 0][j]; v.y = acc[i0 + 1][j];
                    v.z = acc[i0 + 2][j]; v.w = acc[i0 + 3][j];
                    if (RELU) {
                        v.x = fmaxf(v.x, 0.f); v.y = fmaxf(v.y, 0.f);
                        v.z = fmaxf(v.z, 0.f); v.w = fmaxf(v.w, 0.f);
                    }
                    *reinterpret_cast<float4*>(&Out[(size_t)c * M + gm]) = v;
                }
            }
        }
    } else {
#pragma unroll
        for (int i = 0; i < 8; i++) {
            int gm = m0 + tm + i;
            if (gm < M) {
#pragma unroll
                for (int j0 = 0; j0 < 8; j0 += 4) {
                    float4 v;
                    v.x = acc[i][j0 + 0]; v.y = acc[i][j0 + 1];
                    v.z = acc[i][j0 + 2]; v.w = acc[i][j0 + 3];
                    if (RELU) {
                        v.x = fmaxf(v.x, 0.f); v.y = fmaxf(v.y, 0.f);
                        v.z = fmaxf(v.z, 0.f); v.w = fmaxf(v.w, 0.f);
                    }
                    *reinterpret_cast<float4*>(&Out[(size_t)gm * CH + tc + j0]) = v;
                }
            }
        }
    }
}

// ---------------- CSR build (per replay; deterministic up to fp atomics) ----
__global__ void csr_zero() {
    for (int i = blockIdx.x * blockDim.x + threadIdx.x; i < NN; i += gridDim.x * blockDim.x)
        g_cnt[i] = 0;
}

__global__ void csr_count(const int* __restrict__ iInd, const int* __restrict__ jInd) {
    for (int e = blockIdx.x * blockDim.x + threadIdx.x; e < NE; e += gridDim.x * blockDim.x) {
        atomicAdd(&g_cnt[iInd[e]], 1);
        atomicAdd(&g_cnt[jInd[e]], 1);
    }
}

__global__ __launch_bounds__(1024) void csr_scan() {
    const int tid  = threadIdx.x;
    const int lane = tid & 31, wid = tid >> 5;
    __shared__ int wsum[32];
    __shared__ int s_carry;
    if (tid == 0) s_carry = 0;
    __syncthreads();
    for (int base = 0; base < NN; base += 1024) {
        int i = base + tid;
        int v = (i < NN) ? g_cnt[i] : 0;
        int x = v;
#pragma unroll
        for (int off = 1; off < 32; off <<= 1) {
            int t = __shfl_up_sync(0xffffffffu, x, off);
            if (lane >= off) x += t;
        }
        if (lane == 31) wsum[wid] = x;
        __syncthreads();
        if (wid == 0) {
            int w = wsum[lane];
#pragma unroll
            for (int off = 1; off < 32; off <<= 1) {
                int t = __shfl_up_sync(0xffffffffu, w, off);
                if (lane >= off) w += t;
            }
            wsum[lane] = w;
        }
        __syncthreads();
        int excl = s_carry + (wid ? wsum[wid - 1] : 0) + x - v;
        if (i < NN) {
            g_rowptr[i] = excl;
            g_cur[i]    = excl;
        }
        __syncthreads();
        if (tid == 0) s_carry += wsum[31];
        __syncthreads();
    }
    if (threadIdx.x == 0) g_rowptr[NN] = s_carry;
}

__global__ void csr_fill(const int* __restrict__ iInd, const int* __restrict__ jInd) {
    for (int e = blockIdx.x * blockDim.x + threadIdx.x; e < NE; e += gridDim.x * blockDim.x) {
        int p = atomicAdd(&g_cur[iInd[e]], 1);
        g_inc[p] = e;
        int q = atomicAdd(&g_cur[jInd[e]], 1);
        g_inc[q] = e + NE;
    }
}

// ---------------- edge-side kernels (thread.x = channel) --------------------
__global__ void edge_stats(const int* __restrict__ iInd, const int* __restrict__ jInd) {
    const int c  = threadIdx.x;
    const int ty = threadIdx.y;
    __shared__ float ss[4][CH];
    __shared__ float sq[4][CH];
    float s = 0.f, q = 0.f;
    int lane = blockIdx.x * 4 + ty;
    int nl   = gridDim.x * 4;
    for (int e = lane; e < NE; e += nl) {
        int i = __ldg(&iInd[e]);
        int j = __ldg(&jInd[e]);
        float v = g_Yn[i * CH + c] - g_Yn[j * CH + c];
        s += v;
        q += v * v;
    }
    ss[ty][c] = s;
    sq[ty][c] = q;
    __syncthreads();
    if (ty == 0) {
        s = ss[0][c] + ss[1][c] + ss[2][c] + ss[3][c];
        q = sq[0][c] + sq[1][c] + sq[2][c] + sq[3][c];
        atomicAdd(&g_sum[c], s);
        atomicAdd(&g_sumsq[c], q);
    }
}

__global__ void stats_finalize(float count) {
    int c = threadIdx.x;
    float s    = g_sum[c];
    float q    = g_sumsq[c];
    float mean = s / count;
    float var  = q - count * mean * mean;
    g_mean[c] = mean;
    g_inv[c]  = rsqrtf(fmaxf(var, 0.f) + TVEPS);
    g_sum[c]   = 0.f;   // re-zero for next accumulation (deterministic across replays)
    g_sumsq[c] = 0.f;
}

__global__ void edge_apply(const int* __restrict__ iInd, const int* __restrict__ jInd) {
    const int c = threadIdx.x;
    const float mean = g_mean[c];
    const float inv  = g_inv[c];
    int lane = blockIdx.x * 4 + threadIdx.y;
    int nl   = gridDim.x * 4;
    for (int e = lane; e < NE; e += nl) {
        int i = __ldg(&iInd[e]);
        int j = __ldg(&jInd[e]);
        float v = g_Yn[i * CH + c] - g_Yn[j * CH + c];
        float a = (v - mean) * inv;
        size_t idx = (size_t)e * CH + c;
        g_Xe[idx] += HSTEP * fmaxf(a, 0.f);
    }
}

// ---------------- node-side kernels ----------------------------------------
__global__ void node_div() {
    const int c = threadIdx.x;
    int n = blockIdx.x * 4 + threadIdx.y;
    if (n >= NN) return;
    int p0 = g_rowptr[n], p1 = g_rowptr[n + 1];
    float acc = 0.f;
    for (int p = p0; p < p1; p++) {
        int idx = g_inc[p];
        if (idx < NE) acc += g_Xe[(size_t)idx * CH + c];
        else          acc -= g_Xe[(size_t)(idx - NE) * CH + c];
    }
    g_D[n * CH + c] = acc;
}

__global__ void row_stats(const float* __restrict__ X, int M) {
    const int c  = threadIdx.x;
    const int ty = threadIdx.y;
    __shared__ float ss[4][CH];
    __shared__ float sq[4][CH];
    float s = 0.f, q = 0.f;
    int lane = blockIdx.x * 4 + ty;
    int nl   = gridDim.x * 4;
    for (int m = lane; m < M; m += nl) {
        float v = X[(size_t)m * CH + c];
        s += v;
        q += v * v;
    }
    ss[ty][c] = s;
    sq[ty][c] = q;
    __syncthreads();
    if (ty == 0) {
        s = ss[0][c] + ss[1][c] + ss[2][c] + ss[3][c];
        q = sq[0][c] + sq[1][c] + sq[2][c] + sq[3][c];
        atomicAdd(&g_sum[c], s);
        atomicAdd(&g_sumsq[c], q);
    }
}

__global__ void node_apply() {
    int stride = gridDim.x * blockDim.x;
    for (int idx = blockIdx.x * blockDim.x + threadIdx.x; idx < NN * CH; idx += stride) {
        int c   = idx & 127;
        float a = (g_T[idx] - g_mean[c]) * g_inv[c];
        g_Xn[idx] += HSTEP * fmaxf(a, 0.f);
    }
}

// ---------------- launch ----------------------------------------------------
extern "C" void kernel_launch(void* const* d_in, const int* in_sizes, int n_in,
                              void* d_out, int out_size) {
    const float* xn      = (const float*)d_in[0];
    const float* xe      = (const float*)d_in[1];
    const int*   iInd    = (const int*)d_in[2];
    const int*   jInd    = (const int*)d_in[3];
    const float* KNopen  = (const float*)d_in[4];
    const float* KEopen  = (const float*)d_in[5];
    const float* KNclose = (const float*)d_in[6];
    // d_in[7] = KEclose (unused by reference)
    const float* KN      = (const float*)d_in[8];
    const float* KE      = (const float*)d_in[9];
    float*       out     = (float*)d_out;

    (void)in_sizes; (void)n_in; (void)out_size;

    // >48KB dynamic smem for the GEMM variants (idempotent, capture-safe)
    cudaFuncSetAttribute((const void*)gemm128<true,  false, false>,
                         cudaFuncAttributeMaxDynamicSharedMemorySize, GEMM_SMEM);
    cudaFuncSetAttribute((const void*)gemm128<false, false, false>,
                         cudaFuncAttributeMaxDynamicSharedMemorySize, GEMM_SMEM);
    cudaFuncSetAttribute((const void*)gemm128<false, false, true>,
                         cudaFuncAttributeMaxDynamicSharedMemorySize, GEMM_SMEM);
    cudaFuncSetAttribute((const void*)gemm128<false, true,  false>,
                         cudaFuncAttributeMaxDynamicSharedMemorySize, GEMM_SMEM);

    float *pXn, *pYn, *pD, *pT, *pXe;
    cudaGetSymbolAddress((void**)&pXn, g_Xn);
    cudaGetSymbolAddress((void**)&pYn, g_Yn);
    cudaGetSymbolAddress((void**)&pD,  g_D);
    cudaGetSymbolAddress((void**)&pT,  g_T);
    cudaGetSymbolAddress((void**)&pXe, g_Xe);

    const int gN = (NN + 127) / 128;   // 391
    const int gE = (NE + 127) / 128;   // 3907
    const dim3 t128x4(128, 4);

    // CSR build (iInd/jInd constant across replays; rebuilt each replay)
    csr_zero<<<98, 512>>>();
    csr_count<<<592, 256>>>(iInd, jInd);
    csr_scan<<<1, 1024>>>();
    csr_fill<<<592, 256>>>(iInd, jInd);

    // open: Xn = (KNopen @ xn)^T ; Xe = (KEopen @ xe)^T   (to row-major layouts)
    gemm128<true, false, false><<<gN, 256, GEMM_SMEM>>>(xn, KNopen, pXn, NN);
    gemm128<true, false, false><<<gE, 256, GEMM_SMEM>>>(xe, KEopen, pXe, NE);

    for (int l = 0; l < NLAYERS; l++) {
        // Yn = Xn @ KN[l]^T  (node-sized; KN commutes with the edge gather)
        gemm128<false, false, false><<<gN, 256, GEMM_SMEM>>>(pXn, KN + l * CH * CH, pYn, NN);
        // tv_norm stats of KN@grad over edges (gathers from L2-resident Yn)
        edge_stats<<<1184, t128x4>>>(iInd, jInd);
        stats_finalize<<<1, CH>>>((float)NE);
        // xe += H * relu(tv_norm(...))   (recompute gathers, normalize, update)
        edge_apply<<<1184, t128x4>>>(iInd, jInd);
        // d = edge_div(xe) via CSR gather
        node_div<<<(NN + 3) / 4, t128x4>>>();
        // T = relu(d @ KE[l]^T)
        gemm128<false, false, true><<<gN, 256, GEMM_SMEM>>>(pD, KE + l * CH * CH, pT, NN);
        // tv_norm stats of T over nodes
        row_stats<<<592, t128x4>>>(pT, NN);
        stats_finalize<<<1, CH>>>((float)NN);
        // xn += H * relu(tv_norm(T))
        node_apply<<<592, 256>>>();
    }

    // close: out_xn = KNclose @ xn ; out_xe = KNclose @ xe  (channel-major out)
    gemm128<false, true, false><<<gN, 256, GEMM_SMEM>>>(pXn, KNclose, out, NN);
    gemm128<false, true, false><<<gE, 256, GEMM_SMEM>>>(pXe, KNclose, out + (size_t)NN * CH, NE);
}

// round 2
// speedup vs baseline: 1.1123x; 1.1123x over previous
#include <cuda_runtime.h>
#include <cstdint>
#include <cstddef>

#define NN 50000
#define NE 500000
#define CH 128
#define NLAYERS 4
#define HSTEP 0.1f
#define TVEPS 1e-3f

// ---------------- scratch (device globals) ----------------------------------
__device__ float g_Xn  [NN * CH];
__device__ float g_Y4  [NLAYERS * NN * CH];     // Yn per layer (4 x 25.6MB)
__device__ float g_Dacc[NN * CH];               // running edge_div(xe_l), node-sized
__device__ float g_Draw[NN * CH];               // div(xe_raw)
__device__ float g_T   [NN * CH];
__device__ float g_EB  [(size_t)NE * 256];      // [e][0:128]=xeT, [e][128:256]=H*S
__device__ float g_Wc  [CH * 256];              // [c][0:128]=C1=KNclose@KEopen, [c][128:256]=KNclose
__device__ int   g_cnt[NN];
__device__ int   g_rowptr[NN + 1];
__device__ int   g_cur[NN];
__device__ int   g_inc[2 * NE];
__device__ float g_sum[CH];
__device__ float g_sumsq[CH];
__device__ float g_mean4[NLAYERS * CH];
__device__ float g_inv4 [NLAYERS * CH];
__device__ float g_meanN[CH];
__device__ float g_invN [CH];

// ---------------- f32x2 packed FMA helpers ----------------------------------
__device__ __forceinline__ unsigned long long pk2(float x, float y) {
    unsigned long long r;
    asm("mov.b64 %0, {%1, %2};" : "=l"(r) : "f"(x), "f"(y));
    return r;
}
__device__ __forceinline__ void fma2(unsigned long long& d, unsigned long long a,
                                     unsigned long long b) {
    asm("fma.rn.f32x2 %0, %1, %2, %3;" : "=l"(d) : "l"(a), "l"(b), "l"(d));
}
__device__ __forceinline__ float2 upk2(unsigned long long v) {
    float2 r;
    asm("mov.b64 {%0, %1}, %2;" : "=f"(r.x), "=f"(r.y) : "l"(v));
    return r;
}

// ---------------- GEMM: Out[m,c] = sum_k W[c,k] * A(k,m) --------------------
// KD: inner dim (128 or 256). A_CM: A is [k][M] channel-major (input layout),
// else row-major [m][lda]. OUT_CM: Out is [c][M], else [m][CH].
template <int KD, bool A_CM, bool OUT_CM, bool RELU>
__global__ __launch_bounds__(256) void gemm128(const float* __restrict__ A, int lda,
                                               const float* __restrict__ W,
                                               float* __restrict__ Out, int M) {
    extern __shared__ float sm[];
    float* Ws = sm;                 // [KD][132]  Ws[k*132+c] = W[c*KD+k]
    float* As = sm + KD * 132;      // [32][132]

    const int tid = threadIdx.x;
    const int m0  = blockIdx.x * 128;
    const int tc  = (tid & 15) * 8;
    const int tm  = (tid >> 4) * 8;

    for (int i = tid; i < CH * KD; i += 256) {
        int c = i / KD, k = i % KD;
        Ws[k * 132 + c] = W[i];
    }

    unsigned long long acc2[8][4];
    const unsigned long long z = pk2(0.f, 0.f);
#pragma unroll
    for (int i = 0; i < 8; i++)
#pragma unroll
        for (int j = 0; j < 4; j++) acc2[i][j] = z;

    for (int k0 = 0; k0 < KD; k0 += 32) {
        __syncthreads();
        if (A_CM) {
#pragma unroll
            for (int i = tid; i < 32 * 128; i += 256) {
                int kk = i >> 7, m = i & 127;
                int gm = m0 + m;
                As[kk * 132 + m] = (gm < M) ? A[(size_t)(k0 + kk) * M + gm] : 0.f;
            }
        } else {
            int m  = tid >> 1;
            int gm = m0 + m;
            const float4* src = reinterpret_cast<const float4*>(A + (size_t)gm * lda + k0);
#pragma unroll
            for (int j = 0; j < 4; j++) {
                int q = (tid & 1) * 4 + j;
                float4 v = make_float4(0.f, 0.f, 0.f, 0.f);
                if (gm < M) v = src[q];
                As[(q * 4 + 0) * 132 + m] = v.x;
                As[(q * 4 + 1) * 132 + m] = v.y;
                As[(q * 4 + 2) * 132 + m] = v.z;
                As[(q * 4 + 3) * 132 + m] = v.w;
            }
        }
        __syncthreads();
#pragma unroll
        for (int kk = 0; kk < 32; kk++) {
            const float* as = As + kk * 132 + tm;
            float4 alo = *reinterpret_cast<const float4*>(as);
            float4 ahi = *reinterpret_cast<const float4*>(as + 4);
            const unsigned long long* wp =
                reinterpret_cast<const unsigned long long*>(Ws + (size_t)(k0 + kk) * 132 + tc);
            unsigned long long w2[4] = {wp[0], wp[1], wp[2], wp[3]};
            unsigned long long a2[8] = {pk2(alo.x, alo.x), pk2(alo.y, alo.y),
                                        pk2(alo.z, alo.z), pk2(alo.w, alo.w),
                                        pk2(ahi.x, ahi.x), pk2(ahi.y, ahi.y),
                                        pk2(ahi.z, ahi.z), pk2(ahi.w, ahi.w)};
#pragma unroll
            for (int i = 0; i < 8; i++)
#pragma unroll
                for (int j = 0; j < 4; j++) fma2(acc2[i][j], a2[i], w2[j]);
        }
    }

    float accf[8][8];
#pragma unroll
    for (int i = 0; i < 8; i++)
#pragma unroll
        for (int j = 0; j < 4; j++) {
            float2 p = upk2(acc2[i][j]);
            accf[i][2 * j]     = RELU ? fmaxf(p.x, 0.f) : p.x;
            accf[i][2 * j + 1] = RELU ? fmaxf(p.y, 0.f) : p.y;
        }

    if (OUT_CM) {
#pragma unroll
        for (int j = 0; j < 8; j++) {
            int c = tc + j;
#pragma unroll
            for (int i0 = 0; i0 < 8; i0 += 4) {
                int gm = m0 + tm + i0;
                if (gm < M) {  // M % 4 == 0 so full float4 stays in-bounds
                    float4 v = make_float4(accf[i0][j], accf[i0 + 1][j],
                                           accf[i0 + 2][j], accf[i0 + 3][j]);
                    *reinterpret_cast<float4*>(&Out[(size_t)c * M + gm]) = v;
                }
            }
        }
    } else {
#pragma unroll
        for (int i = 0; i < 8; i++) {
            int gm = m0 + tm + i;
            if (gm < M) {
#pragma unroll
                for (int j0 = 0; j0 < 8; j0 += 4) {
                    float4 v = make_float4(accf[i][j0], accf[i][j0 + 1],
                                           accf[i][j0 + 2], accf[i][j0 + 3]);
                    *reinterpret_cast<float4*>(&Out[(size_t)gm * CH + tc + j0]) = v;
                }
            }
        }
    }
}

// ---------------- CSR build --------------------------------------------------
__global__ void csr_zero() {
    for (int i = blockIdx.x * blockDim.x + threadIdx.x; i < NN; i += gridDim.x * blockDim.x)
        g_cnt[i] = 0;
}
__global__ void csr_count(const int* __restrict__ iInd, const int* __restrict__ jInd) {
    for (int e = blockIdx.x * blockDim.x + threadIdx.x; e < NE; e += gridDim.x * blockDim.x) {
        atomicAdd(&g_cnt[iInd[e]], 1);
        atomicAdd(&g_cnt[jInd[e]], 1);
    }
}
__global__ __launch_bounds__(1024) void csr_scan() {
    const int tid = threadIdx.x, lane = tid & 31, wid = tid >> 5;
    __shared__ int wsum[32];
    __shared__ int s_carry;
    if (tid == 0) s_carry = 0;
    __syncthreads();
    for (int base = 0; base < NN; base += 1024) {
        int i = base + tid;
        int v = (i < NN) ? g_cnt[i] : 0;
        int x = v;
#pragma unroll
        for (int off = 1; off < 32; off <<= 1) {
            int t = __shfl_up_sync(0xffffffffu, x, off);
            if (lane >= off) x += t;
        }
        if (lane == 31) wsum[wid] = x;
        __syncthreads();
        if (wid == 0) {
            int w = wsum[lane];
#pragma unroll
            for (int off = 1; off < 32; off <<= 1) {
                int t = __shfl_up_sync(0xffffffffu, w, off);
                if (lane >= off) w += t;
            }
            wsum[lane] = w;
        }
        __syncthreads();
        int excl = s_carry + (wid ? wsum[wid - 1] : 0) + x - v;
        if (i < NN) { g_rowptr[i] = excl; g_cur[i] = excl; }
        __syncthreads();
        if (tid == 0) s_carry += wsum[31];
        __syncthreads();
    }
    if (threadIdx.x == 0) g_rowptr[NN] = s_carry;
}
__global__ void csr_fill(const int* __restrict__ iInd, const int* __restrict__ jInd) {
    for (int e = blockIdx.x * blockDim.x + threadIdx.x; e < NE; e += gridDim.x * blockDim.x) {
        int p = atomicAdd(&g_cur[iInd[e]], 1); g_inc[p] = e;
        int q = atomicAdd(&g_cur[jInd[e]], 1); g_inc[q] = e + NE;
    }
}

// ---------------- transpose raw xe (CM -> row-major into g_EB cols 0:128) ---
__global__ void transpose_xe(const float* __restrict__ xe) {
    __shared__ float tile[32][33];
    int e0 = blockIdx.x * 32, c0 = blockIdx.y * 32;
    int tx = threadIdx.x, ty = threadIdx.y;
    for (int r = ty; r < 32; r += 8) {
        int e = e0 + tx;
        tile[r][tx] = (e < NE) ? xe[(size_t)(c0 + r) * NE + e] : 0.f;
    }
    __syncthreads();
    for (int r = ty; r < 32; r += 8) {
        int e = e0 + r;
        if (e < NE) g_EB[(size_t)e * 256 + c0 + tx] = tile[tx][r];
    }
}

// ---------------- div of raw edges (CSR) ------------------------------------
__global__ void div_raw() {
    const int c = threadIdx.x;
    int n = blockIdx.x * 4 + threadIdx.y;
    if (n >= NN) return;
    int p0 = g_rowptr[n], p1 = g_rowptr[n + 1];
    float acc = 0.f;
    for (int p = p0; p < p1; p++) {
        int idx = g_inc[p];
        if (idx < NE) acc += g_EB[(size_t)idx * 256 + c];
        else          acc -= g_EB[(size_t)(idx - NE) * 256 + c];
    }
    g_Draw[n * CH + c] = acc;
}

// ---------------- combined close weights: Wc = [KNclose@KEopen | KNclose] ---
__global__ void make_wc(const float* __restrict__ KNclose, const float* __restrict__ KEopen) {
    __shared__ float row[CH];
    int c = blockIdx.x, k = threadIdx.x;
    row[k] = KNclose[c * CH + k];
    __syncthreads();
    float acc = 0.f;
    for (int t = 0; t < CH; t++) acc = fmaf(row[t], KEopen[t * CH + k], acc);
    g_Wc[c * 256 + k]      = acc;
    g_Wc[c * 256 + 128 + k] = row[k];
}

// ---------------- tv_norm stats ---------------------------------------------
__global__ void edge_stats(const int* __restrict__ iInd, const int* __restrict__ jInd,
                           const float* __restrict__ Y) {
    const int c = threadIdx.x, ty = threadIdx.y;
    __shared__ float ss[4][CH], sq[4][CH];
    float s = 0.f, q = 0.f;
    int lane = blockIdx.x * 4 + ty, nl = gridDim.x * 4;
    for (int e = lane; e < NE; e += nl) {
        int i = __ldg(&iInd[e]), j = __ldg(&jInd[e]);
        float v = Y[i * CH + c] - Y[j * CH + c];
        s += v; q += v * v;
    }
    ss[ty][c] = s; sq[ty][c] = q;
    __syncthreads();
    if (ty == 0) {
        atomicAdd(&g_sum[c],   ss[0][c] + ss[1][c] + ss[2][c] + ss[3][c]);
        atomicAdd(&g_sumsq[c], sq[0][c] + sq[1][c] + sq[2][c] + sq[3][c]);
    }
}

__global__ void row_stats(const float* __restrict__ X, int M) {
    const int c = threadIdx.x, ty = threadIdx.y;
    __shared__ float ss[4][CH], sq[4][CH];
    float s = 0.f, q = 0.f;
    int lane = blockIdx.x * 4 + ty, nl = gridDim.x * 4;
    for (int m = lane; m < M; m += nl) {
        float v = X[(size_t)m * CH + c];
        s += v; q += v * v;
    }
    ss[ty][c] = s; sq[ty][c] = q;
    __syncthreads();
    if (ty == 0) {
        atomicAdd(&g_sum[c],   ss[0][c] + ss[1][c] + ss[2][c] + ss[3][c]);
        atomicAdd(&g_sumsq[c], sq[0][c] + sq[1][c] + sq[2][c] + sq[3][c]);
    }
}

__global__ void stats_finalize(float count, float* __restrict__ meanOut,
                               float* __restrict__ invOut) {
    int c = threadIdx.x;
    float s = g_sum[c], q = g_sumsq[c];
    float mean = s / count;
    float var  = q - count * mean * mean;
    meanOut[c] = mean;
    invOut[c]  = rsqrtf(fmaxf(var, 0.f) + TVEPS);
    g_sum[c] = 0.f;
    g_sumsq[c] = 0.f;
}

// ---------------- per-layer div(relu(A_l)) via CSR, accumulate into Dacc ----
__global__ void div_relu(const int* __restrict__ iInd, const int* __restrict__ jInd,
                         const float* __restrict__ Y, const float* __restrict__ mean,
                         const float* __restrict__ inv) {
    const int c = threadIdx.x;
    int n = blockIdx.x * 4 + threadIdx.y;
    if (n >= NN) return;
    const float mc = mean[c], ic = inv[c];
    int p0 = g_rowptr[n], p1 = g_rowptr[n + 1];
    float acc = 0.f;
    for (int p = p0; p < p1; p++) {
        int idx  = g_inc[p];
        int e    = (idx < NE) ? idx : idx - NE;
        float sg = (idx < NE) ? 1.f : -1.f;
        int i = __ldg(&iInd[e]), j = __ldg(&jInd[e]);
        float v = Y[i * CH + c] - Y[j * CH + c];
        float a = fmaxf((v - mc) * ic, 0.f);
        acc += sg * a;
    }
    g_Dacc[n * CH + c] += HSTEP * acc;
}

// ---------------- node update ------------------------------------------------
__global__ void node_apply() {
    int stride = gridDim.x * blockDim.x;
    for (int idx = blockIdx.x * blockDim.x + threadIdx.x; idx < NN * CH; idx += stride) {
        int c   = idx & 127;
        float a = (g_T[idx] - g_meanN[c]) * g_invN[c];
        g_Xn[idx] += HSTEP * fmaxf(a, 0.f);
    }
}

// ---------------- final S_e = H * sum_l relu(A_l) into g_EB cols 128:256 ----
__global__ void build_S(const int* __restrict__ iInd, const int* __restrict__ jInd) {
    const int c = threadIdx.x;
    float mc[NLAYERS], ic[NLAYERS];
#pragma unroll
    for (int l = 0; l < NLAYERS; l++) { mc[l] = g_mean4[l * CH + c]; ic[l] = g_inv4[l * CH + c]; }
    int lane = blockIdx.x * 4 + threadIdx.y, nl = gridDim.x * 4;
    for (int e = lane; e < NE; e += nl) {
        int i = __ldg(&iInd[e]), j = __ldg(&jInd[e]);
        float s = 0.f;
#pragma unroll
        for (int l = 0; l < NLAYERS; l++) {
            const float* Y = g_Y4 + (size_t)l * NN * CH;
            float v = Y[i * CH + c] - Y[j * CH + c];
            s += fmaxf((v - mc[l]) * ic[l], 0.f);
        }
        g_EB[(size_t)e * 256 + 128 + c] = HSTEP * s;
    }
}

// ---------------- launch -----------------------------------------------------
extern "C" void kernel_launch(void* const* d_in, const int* in_sizes, int n_in,
                              void* d_out, int out_size) {
    const float* xn      = (const float*)d_in[0];
    const float* xe      = (const float*)d_in[1];
    const int*   iInd    = (const int*)d_in[2];
    const int*   jInd    = (const int*)d_in[3];
    const float* KNopen  = (const float*)d_in[4];
    const float* KEopen  = (const float*)d_in[5];
    const float* KNclose = (const float*)d_in[6];
    const float* KN      = (const float*)d_in[8];
    const float* KE      = (const float*)d_in[9];
    float*       out     = (float*)d_out;
    (void)in_sizes; (void)n_in; (void)out_size;

    const int S1 = (128 * 132 + 32 * 132) * 4;  // 84.5 KB
    const int S2 = (256 * 132 + 32 * 132) * 4;  // 152 KB
    cudaFuncSetAttribute((const void*)gemm128<128, true,  false, false>,
                         cudaFuncAttributeMaxDynamicSharedMemorySize, S1);
    cudaFuncSetAttribute((const void*)gemm128<128, false, false, false>,
                         cudaFuncAttributeMaxDynamicSharedMemorySize, S1);
    cudaFuncSetAttribute((const void*)gemm128<128, false, false, true>,
                         cudaFuncAttributeMaxDynamicSharedMemorySize, S1);
    cudaFuncSetAttribute((const void*)gemm128<128, false, true,  false>,
                         cudaFuncAttributeMaxDynamicSharedMemorySize, S1);
    cudaFuncSetAttribute((const void*)gemm128<256, false, true,  false>,
                         cudaFuncAttributeMaxDynamicSharedMemorySize, S2);

    float *pXn, *pY4, *pDacc, *pDraw, *pT, *pWc, *pM4, *pI4, *pMN, *pIN;
    cudaGetSymbolAddress((void**)&pXn,   g_Xn);
    cudaGetSymbolAddress((void**)&pY4,   g_Y4);
    cudaGetSymbolAddress((void**)&pDacc, g_Dacc);
    cudaGetSymbolAddress((void**)&pDraw, g_Draw);
    cudaGetSymbolAddress((void**)&pT,    g_T);
    cudaGetSymbolAddress((void**)&pWc,   g_Wc);
    cudaGetSymbolAddress((void**)&pM4,   g_mean4);
    cudaGetSymbolAddress((void**)&pI4,   g_inv4);
    cudaGetSymbolAddress((void**)&pMN,   g_meanN);
    cudaGetSymbolAddress((void**)&pIN,   g_invN);
    float* pEB;
    cudaGetSymbolAddress((void**)&pEB,   g_EB);

    const int gN = (NN + 127) / 128;   // 391
    const int gE = (NE + 127) / 128;   // 3907
    const dim3 t128x4(128, 4);

    // CSR + raw-edge preprocessing
    csr_zero<<<98, 512>>>();
    csr_count<<<592, 256>>>(iInd, jInd);
    csr_scan<<<1, 1024>>>();
    csr_fill<<<592, 256>>>(iInd, jInd);
    transpose_xe<<<dim3((NE + 31) / 32, 4), dim3(32, 8)>>>(xe);
    div_raw<<<(NN + 3) / 4, t128x4>>>();
    make_wc<<<128, 128>>>(KNclose, KEopen);

    // open node GEMM + D0 = KEopen @ div(xe_raw)
    gemm128<128, true,  false, false><<<gN, 256, S1>>>(xn, 0, KNopen, pXn, NN);
    gemm128<128, false, false, false><<<gN, 256, S1>>>(pDraw, 128, KEopen, pDacc, NN);

    for (int l = 0; l < NLAYERS; l++) {
        float* Yl = pY4 + (size_t)l * NN * CH;
        gemm128<128, false, false, false><<<gN, 256, S1>>>(pXn, 128, KN + l * CH * CH, Yl, NN);
        edge_stats<<<1184, t128x4>>>(iInd, jInd, Yl);
        stats_finalize<<<1, CH>>>((float)NE, pM4 + l * CH, pI4 + l * CH);
        div_relu<<<(NN + 3) / 4, t128x4>>>(iInd, jInd, Yl, pM4 + l * CH, pI4 + l * CH);
        gemm128<128, false, false, true><<<gN, 256, S1>>>(pDacc, 128, KE + l * CH * CH, pT, NN);
        row_stats<<<592, t128x4>>>(pT, NN);
        stats_finalize<<<1, CH>>>((float)NN, pMN, pIN);
        node_apply<<<592, 256>>>();
    }

    // S_e (cols 128:256 of g_EB), then both closes
    build_S<<<1184, t128x4>>>(iInd, jInd);
    gemm128<128, false, true, false><<<gN, 256, S1>>>(pXn, 128, KNclose, out, NN);
    gemm128<256, false, true, false><<<gE, 256, S2>>>(pEB, 256, pWc, out + (size_t)NN * CH, NE);
}

// round 6
// speedup vs baseline: 1.4876x; 1.3373x over previous
#include <cuda_runtime.h>
#include <cstdint>
#include <cstddef>

#define NN 50000
#define NE 500000
#define CH 128
#define NLAYERS 4
#define HSTEP 0.1f
#define TVEPS 1e-3f

// ---------------- scratch (device globals; no allocations allowed) ----------
__device__ float g_Xn  [NN * CH];
__device__ float g_Y4  [NLAYERS * NN * CH];
__device__ float g_Dacc[NN * CH];
__device__ float g_Draw[NN * CH];
__device__ float g_T   [NN * CH];
__device__ float g_EB  [(size_t)NE * 256];   // [e][0:128]=xeT, [e][128:256]=H*S
__device__ float g_Wc  [CH * 256];           // [c][0:128]=KNclose@KEopen, [c][128:256]=KNclose
__device__ int   g_cnt[NN];
__device__ int   g_rowptr[NN + 1];
__device__ int   g_cur[NN];
__device__ int   g_inc[2 * NE];
__device__ float g_sum[CH];
__device__ float g_sumsq[CH];
__device__ float g_mean4[NLAYERS * CH];
__device__ float g_inv4 [NLAYERS * CH];
__device__ float g_meanN[CH];
__device__ float g_invN [CH];

// ================= helpers ===================================================
__device__ __forceinline__ uint32_t smem_u32(const void* p) {
    uint32_t a;
    asm("{ .reg .u64 t; cvta.to.shared.u64 t, %1; cvt.u32.u64 %0, t; }" : "=r"(a) : "l"(p));
    return a;
}

// bf16 hi/lo split of 8 consecutive fp32 -> two uint4 (8 bf16 each)
__device__ __forceinline__ void split8(const float* x, uint4& hv, uint4& lv) {
    uint32_t h[4], l[4];
#pragma unroll
    for (int p = 0; p < 4; p++) {
        float x0 = x[2 * p], x1 = x[2 * p + 1];
        uint32_t hp;
        asm("cvt.rn.satfinite.bf16x2.f32 %0, %1, %2;" : "=r"(hp) : "f"(x1), "f"(x0));
        float h0 = __uint_as_float(hp << 16);
        float h1 = __uint_as_float(hp & 0xffff0000u);
        float r0 = x0 - h0, r1 = x1 - h1;
        uint32_t lp;
        asm("cvt.rn.satfinite.bf16x2.f32 %0, %1, %2;" : "=r"(lp) : "f"(r1), "f"(r0));
        h[p] = hp; l[p] = lp;
    }
    hv = make_uint4(h[0], h[1], h[2], h[3]);
    lv = make_uint4(l[0], l[1], l[2], l[3]);
}

__device__ __forceinline__ void ldsm4(uint32_t* r, uint32_t addr) {
    asm volatile("ldmatrix.sync.aligned.m8n8.x4.shared.b16 {%0,%1,%2,%3}, [%4];"
                 : "=r"(r[0]), "=r"(r[1]), "=r"(r[2]), "=r"(r[3]) : "r"(addr));
}
__device__ __forceinline__ void mma16816(float* c, const uint32_t* a, const uint32_t* b) {
    asm volatile(
        "mma.sync.aligned.m16n8k16.row.col.f32.bf16.bf16.f32 "
        "{%0,%1,%2,%3}, {%4,%5,%6,%7}, {%8,%9}, {%0,%1,%2,%3};"
        : "+f"(c[0]), "+f"(c[1]), "+f"(c[2]), "+f"(c[3])
        : "r"(a[0]), "r"(a[1]), "r"(a[2]), "r"(a[3]), "r"(b[0]), "r"(b[1]));
}

// ================= MMA GEMM: Out[m,c] = sum_k W[c,k]*A[m,k] ==================
// A fp32 row-major [m][KD]; W fp32 row-major [c][KD]. bf16 split, 3 terms.
#define STR 136                       // bf16 elements per smem row (conflict-free ldmatrix)
#define TILE_U16 (128 * STR)
#define MMA_SMEM (4 * TILE_U16 * 2)   // Ah, Al, Wh, Wl = 139264 B

template <int KD, bool OUT_CM, bool RELU>
__global__ __launch_bounds__(256, 1) void mma_gemm(const float* __restrict__ A,
                                                   const float* __restrict__ W,
                                                   float* __restrict__ Out, int M) {
    extern __shared__ char smc[];
    uint16_t* Ah = reinterpret_cast<uint16_t*>(smc);
    uint16_t* Al = Ah + TILE_U16;
    uint16_t* Wh = Al + TILE_U16;
    uint16_t* Wl = Wh + TILE_U16;

    const int tid = threadIdx.x, lane = tid & 31, wid = tid >> 5;
    const int m0 = blockIdx.x * 128;
    const int wm = (wid >> 2) * 64;   // warp m-origin (0 or 64)
    const int wn = (wid & 3) * 32;    // warp n-origin (0,32,64,96)

    float acc[4][4][4];
#pragma unroll
    for (int i = 0; i < 4; i++)
#pragma unroll
        for (int j = 0; j < 4; j++)
#pragma unroll
            for (int q = 0; q < 4; q++) acc[i][j][q] = 0.f;

    // ldmatrix per-lane byte offsets within a tile
    const uint32_t aoff = (uint32_t)(((lane & 15) * STR + (lane >> 4) * 8) * 2);
    const uint32_t boff = (uint32_t)((((lane & 7) + ((lane >> 4) << 3)) * STR +
                                      ((lane >> 3) & 1) * 8) * 2);
    const uint32_t sAh = smem_u32(Ah), sAl = smem_u32(Al);
    const uint32_t sWh = smem_u32(Wh), sWl = smem_u32(Wl);

    const int NCHUNK = KD / 128;
    for (int ci = 0; ci < NCHUNK; ci++) {
        __syncthreads();
        // stage W chunk (fp32 -> bf16 hi/lo)
        for (int G = tid; G < 2048; G += 256) {
            int r = G >> 4, k8 = (G & 15) * 8;
            const float4* s = reinterpret_cast<const float4*>(W + (size_t)r * KD + ci * 128 + k8);
            float4 a = s[0], b = s[1];
            float xv[8] = {a.x, a.y, a.z, a.w, b.x, b.y, b.z, b.w};
            uint4 hv, lv;
            split8(xv, hv, lv);
            *reinterpret_cast<uint4*>(Wh + r * STR + k8) = hv;
            *reinterpret_cast<uint4*>(Wl + r * STR + k8) = lv;
        }
        // stage A chunk
        for (int G = tid; G < 2048; G += 256) {
            int r = G >> 4, k8 = (G & 15) * 8;
            int gm = m0 + r;
            float xv[8] = {0.f, 0.f, 0.f, 0.f, 0.f, 0.f, 0.f, 0.f};
            if (gm < M) {
                const float4* s =
                    reinterpret_cast<const float4*>(A + (size_t)gm * KD + ci * 128 + k8);
                float4 a = s[0], b = s[1];
                xv[0] = a.x; xv[1] = a.y; xv[2] = a.z; xv[3] = a.w;
                xv[4] = b.x; xv[5] = b.y; xv[6] = b.z; xv[7] = b.w;
            }
            uint4 hv, lv;
            split8(xv, hv, lv);
            *reinterpret_cast<uint4*>(Ah + r * STR + k8) = hv;
            *reinterpret_cast<uint4*>(Al + r * STR + k8) = lv;
        }
        __syncthreads();

#pragma unroll
        for (int ks = 0; ks < 8; ks++) {
            const uint32_t k0b = (uint32_t)(ks * 32);   // 16 bf16 = 32 bytes
            uint32_t AhF[4][4], AlF[4][4], WhF[2][4], WlF[2][4];
#pragma unroll
            for (int mi = 0; mi < 4; mi++) {
                uint32_t ro = (uint32_t)((wm + mi * 16) * STR * 2) + aoff + k0b;
                ldsm4(AhF[mi], sAh + ro);
                ldsm4(AlF[mi], sAl + ro);
            }
#pragma unroll
            for (int p = 0; p < 2; p++) {
                uint32_t ro = (uint32_t)((wn + p * 16) * STR * 2) + boff + k0b;
                ldsm4(WhF[p], sWh + ro);
                ldsm4(WlF[p], sWl + ro);
            }
#pragma unroll
            for (int mi = 0; mi < 4; mi++)
#pragma unroll
                for (int ni = 0; ni < 4; ni++) {
                    const uint32_t* bh = &WhF[ni >> 1][(ni & 1) * 2];
                    const uint32_t* bl = &WlF[ni >> 1][(ni & 1) * 2];
                    mma16816(acc[mi][ni], AhF[mi], bh);   // hi*hi
                    mma16816(acc[mi][ni], AhF[mi], bl);   // hi*lo
                    mma16816(acc[mi][ni], AlF[mi], bh);   // lo*hi
                }
        }
    }

    // epilogue
    const int g = lane >> 2, tq = lane & 3;
#pragma unroll
    for (int mi = 0; mi < 4; mi++) {
        int m = m0 + wm + mi * 16 + g;
#pragma unroll
        for (int ni = 0; ni < 4; ni++) {
            int n = wn + ni * 8 + tq * 2;
            float c0 = acc[mi][ni][0], c1 = acc[mi][ni][1];
            float c2 = acc[mi][ni][2], c3 = acc[mi][ni][3];
            if (RELU) {
                c0 = fmaxf(c0, 0.f); c1 = fmaxf(c1, 0.f);
                c2 = fmaxf(c2, 0.f); c3 = fmaxf(c3, 0.f);
            }
            if (OUT_CM) {
                if (m < M)     { Out[(size_t)n * M + m]           = c0;
                                 Out[(size_t)(n + 1) * M + m]     = c1; }
                if (m + 8 < M) { Out[(size_t)n * M + m + 8]       = c2;
                                 Out[(size_t)(n + 1) * M + m + 8] = c3; }
            } else {
                if (m < M)
                    *reinterpret_cast<float2*>(&Out[(size_t)m * CH + n]) = make_float2(c0, c1);
                if (m + 8 < M)
                    *reinterpret_cast<float2*>(&Out[(size_t)(m + 8) * CH + n]) = make_float2(c2, c3);
            }
        }
    }
}

// ================= f32x2 GEMM (CM-input open GEMM only) =====================
__device__ __forceinline__ unsigned long long pk2(float x, float y) {
    unsigned long long r;
    asm("mov.b64 %0, {%1, %2};" : "=l"(r) : "f"(x), "f"(y));
    return r;
}
__device__ __forceinline__ void fma2(unsigned long long& d, unsigned long long a,
                                     unsigned long long b) {
    asm("fma.rn.f32x2 %0, %1, %2, %3;" : "=l"(d) : "l"(a), "l"(b), "l"(d));
}
__device__ __forceinline__ float2 upk2(unsigned long long v) {
    float2 r;
    asm("mov.b64 {%0, %1}, %2;" : "=f"(r.x), "=f"(r.y) : "l"(v));
    return r;
}

#define GEMM_SMEM ((128 * 132 + 32 * 132) * 4)
__global__ __launch_bounds__(256) void gemm_open(const float* __restrict__ A,
                                                 const float* __restrict__ W,
                                                 float* __restrict__ Out, int M) {
    extern __shared__ float sm[];
    float* Ws = sm;
    float* As = sm + 128 * 132;
    const int tid = threadIdx.x;
    const int m0  = blockIdx.x * 128;
    const int tc  = (tid & 15) * 8;
    const int tm  = (tid >> 4) * 8;
    for (int i = tid; i < CH * CH; i += 256) {
        int c = i >> 7, k = i & 127;
        Ws[k * 132 + c] = W[i];
    }
    unsigned long long acc2[8][4];
    const unsigned long long z = pk2(0.f, 0.f);
#pragma unroll
    for (int i = 0; i < 8; i++)
#pragma unroll
        for (int j = 0; j < 4; j++) acc2[i][j] = z;
    for (int k0 = 0; k0 < CH; k0 += 32) {
        __syncthreads();
#pragma unroll
        for (int i = tid; i < 32 * 128; i += 256) {
            int kk = i >> 7, m = i & 127;
            int gm = m0 + m;
            As[kk * 132 + m] = (gm < M) ? A[(size_t)(k0 + kk) * M + gm] : 0.f;
        }
        __syncthreads();
#pragma unroll
        for (int kk = 0; kk < 32; kk++) {
            const float* as = As + kk * 132 + tm;
            float4 alo = *reinterpret_cast<const float4*>(as);
            float4 ahi = *reinterpret_cast<const float4*>(as + 4);
            const unsigned long long* wp =
                reinterpret_cast<const unsigned long long*>(Ws + (size_t)(k0 + kk) * 132 + tc);
            unsigned long long w2[4] = {wp[0], wp[1], wp[2], wp[3]};
            unsigned long long a2[8] = {pk2(alo.x, alo.x), pk2(alo.y, alo.y),
                                        pk2(alo.z, alo.z), pk2(alo.w, alo.w),
                                        pk2(ahi.x, ahi.x), pk2(ahi.y, ahi.y),
                                        pk2(ahi.z, ahi.z), pk2(ahi.w, ahi.w)};
#pragma unroll
            for (int i = 0; i < 8; i++)
#pragma unroll
                for (int j = 0; j < 4; j++) fma2(acc2[i][j], a2[i], w2[j]);
        }
    }
#pragma unroll
    for (int i = 0; i < 8; i++) {
        int gm = m0 + tm + i;
        if (gm < M) {
            float o[8];
#pragma unroll
            for (int j = 0; j < 4; j++) {
                float2 p = upk2(acc2[i][j]);
                o[2 * j] = p.x; o[2 * j + 1] = p.y;
            }
#pragma unroll
            for (int j0 = 0; j0 < 8; j0 += 4)
                *reinterpret_cast<float4*>(&Out[(size_t)gm * CH + tc + j0]) =
                    make_float4(o[j0], o[j0 + 1], o[j0 + 2], o[j0 + 3]);
        }
    }
}

// ================= CSR build =================================================
__global__ void csr_zero() {
    for (int i = blockIdx.x * blockDim.x + threadIdx.x; i < NN; i += gridDim.x * blockDim.x)
        g_cnt[i] = 0;
}
__global__ void csr_count(const int* __restrict__ iInd, const int* __restrict__ jInd) {
    for (int e = blockIdx.x * blockDim.x + threadIdx.x; e < NE; e += gridDim.x * blockDim.x) {
        atomicAdd(&g_cnt[iInd[e]], 1);
        atomicAdd(&g_cnt[jInd[e]], 1);
    }
}
__global__ __launch_bounds__(1024) void csr_scan() {
    const int tid = threadIdx.x, lane = tid & 31, wid = tid >> 5;
    __shared__ int wsum[32];
    __shared__ int s_carry;
    if (tid == 0) s_carry = 0;
    __syncthreads();
    for (int base = 0; base < NN; base += 1024) {
        int i = base + tid;
        int v = (i < NN) ? g_cnt[i] : 0;
        int x = v;
#pragma unroll
        for (int off = 1; off < 32; off <<= 1) {
            int t = __shfl_up_sync(0xffffffffu, x, off);
            if (lane >= off) x += t;
        }
        if (lane == 31) wsum[wid] = x;
        __syncthreads();
        if (wid == 0) {
            int w = wsum[lane];
#pragma unroll
            for (int off = 1; off < 32; off <<= 1) {
                int t = __shfl_up_sync(0xffffffffu, w, off);
                if (lane >= off) w += t;
            }
            wsum[lane] = w;
        }
        __syncthreads();
        int excl = s_carry + (wid ? wsum[wid - 1] : 0) + x - v;
        if (i < NN) { g_rowptr[i] = excl; g_cur[i] = excl; }
        __syncthreads();
        if (tid == 0) s_carry += wsum[31];
        __syncthreads();
    }
    if (threadIdx.x == 0) g_rowptr[NN] = s_carry;
}
__global__ void csr_fill(const int* __restrict__ iInd, const int* __restrict__ jInd) {
    for (int e = blockIdx.x * blockDim.x + threadIdx.x; e < NE; e += gridDim.x * blockDim.x) {
        int p = atomicAdd(&g_cur[iInd[e]], 1); g_inc[p] = e;
        int q = atomicAdd(&g_cur[jInd[e]], 1); g_inc[q] = e + NE;
    }
}

// ---------------- transpose raw xe (CM -> g_EB cols 0:128) ------------------
__global__ void transpose_xe(const float* __restrict__ xe) {
    __shared__ float tile[32][33];
    int e0 = blockIdx.x * 32, c0 = blockIdx.y * 32;
    int tx = threadIdx.x, ty = threadIdx.y;
    for (int r = ty; r < 32; r += 8) {
        int e = e0 + tx;
        tile[r][tx] = (e < NE) ? xe[(size_t)(c0 + r) * NE + e] : 0.f;
    }
    __syncthreads();
    for (int r = ty; r < 32; r += 8) {
        int e = e0 + r;
        if (e < NE) g_EB[(size_t)e * 256 + c0 + tx] = tile[tx][r];
    }
}

__global__ void div_raw() {
    const int c = threadIdx.x;
    int n = blockIdx.x * 4 + threadIdx.y;
    if (n >= NN) return;
    int p0 = g_rowptr[n], p1 = g_rowptr[n + 1];
    float acc = 0.f;
    for (int p = p0; p < p1; p++) {
        int idx = g_inc[p];
        if (idx < NE) acc += g_EB[(size_t)idx * 256 + c];
        else          acc -= g_EB[(size_t)(idx - NE) * 256 + c];
    }
    g_Draw[n * CH + c] = acc;
}

__global__ void make_wc(const float* __restrict__ KNclose, const float* __restrict__ KEopen) {
    __shared__ float row[CH];
    int c = blockIdx.x, k = threadIdx.x;
    row[k] = KNclose[c * CH + k];
    __syncthreads();
    float acc = 0.f;
    for (int t = 0; t < CH; t++) acc = fmaf(row[t], KEopen[t * CH + k], acc);
    g_Wc[c * 256 + k]       = acc;
    g_Wc[c * 256 + 128 + k] = row[k];
}

// ---------------- tv_norm stats ---------------------------------------------
__global__ void edge_stats(const int* __restrict__ iInd, const int* __restrict__ jInd,
                           const float* __restrict__ Y) {
    const int c = threadIdx.x, ty = threadIdx.y;
    __shared__ float ss[4][CH], sq[4][CH];
    float s = 0.f, q = 0.f;
    int lane = blockIdx.x * 4 + ty, nl = gridDim.x * 4;
    for (int e = lane; e < NE; e += nl) {
        int i = __ldg(&iInd[e]), j = __ldg(&jInd[e]);
        float v = Y[i * CH + c] - Y[j * CH + c];
        s += v; q += v * v;
    }
    ss[ty][c] = s; sq[ty][c] = q;
    __syncthreads();
    if (ty == 0) {
        atomicAdd(&g_sum[c],   ss[0][c] + ss[1][c] + ss[2][c] + ss[3][c]);
        atomicAdd(&g_sumsq[c], sq[0][c] + sq[1][c] + sq[2][c] + sq[3][c]);
    }
}
__global__ void row_stats(const float* __restrict__ X, int M) {
    const int c = threadIdx.x, ty = threadIdx.y;
    __shared__ float ss[4][CH], sq[4][CH];
    float s = 0.f, q = 0.f;
    int lane = blockIdx.x * 4 + ty, nl = gridDim.x * 4;
    for (int m = lane; m < M; m += nl) {
        float v = X[(size_t)m * CH + c];
        s += v; q += v * v;
    }
    ss[ty][c] = s; sq[ty][c] = q;
    __syncthreads();
    if (ty == 0) {
        atomicAdd(&g_sum[c],   ss[0][c] + ss[1][c] + ss[2][c] + ss[3][c]);
        atomicAdd(&g_sumsq[c], sq[0][c] + sq[1][c] + sq[2][c] + sq[3][c]);
    }
}
__global__ void stats_finalize(float count, float* __restrict__ meanOut,
                               float* __restrict__ invOut) {
    int c = threadIdx.x;
    float s = g_sum[c], q = g_sumsq[c];
    float mean = s / count;
    float var  = q - count * mean * mean;
    meanOut[c] = mean;
    invOut[c]  = rsqrtf(fmaxf(var, 0.f) + TVEPS);
    g_sum[c] = 0.f; g_sumsq[c] = 0.f;
}

// ---------------- per-layer div(relu(A_l)); own row cached in regs ----------
__global__ void div_relu(const int* __restrict__ iInd, const int* __restrict__ jInd,
                         const float* __restrict__ Y, const float* __restrict__ mean,
                         const float* __restrict__ inv) {
    const int c = threadIdx.x;
    int n = blockIdx.x * 4 + threadIdx.y;
    if (n >= NN) return;
    const float mc = mean[c], ic = inv[c];
    const float yn = Y[n * CH + c];
    int p0 = g_rowptr[n], p1 = g_rowptr[n + 1];
    float acc = 0.f;
    for (int p = p0; p < p1; p++) {
        int idx = g_inc[p];
        if (idx < NE) {                      // n == iInd[idx]
            int o = __ldg(&jInd[idx]);
            float v = yn - Y[o * CH + c];
            acc += fmaxf((v - mc) * ic, 0.f);
        } else {                             // n == jInd[idx-NE]
            int e = idx - NE;
            int o = __ldg(&iInd[e]);
            float v = Y[o * CH + c] - yn;
            acc -= fmaxf((v - mc) * ic, 0.f);
        }
    }
    g_Dacc[n * CH + c] += HSTEP * acc;
}

__global__ void node_apply() {
    int stride = gridDim.x * blockDim.x;
    for (int idx = blockIdx.x * blockDim.x + threadIdx.x; idx < NN * CH; idx += stride) {
        int c   = idx & 127;
        float a = (g_T[idx] - g_meanN[c]) * g_invN[c];
        g_Xn[idx] += HSTEP * fmaxf(a, 0.f);
    }
}

__global__ void build_S(const int* __restrict__ iInd, const int* __restrict__ jInd) {
    const int c = threadIdx.x;
    float mc[NLAYERS], ic[NLAYERS];
#pragma unroll
    for (int l = 0; l < NLAYERS; l++) { mc[l] = g_mean4[l * CH + c]; ic[l] = g_inv4[l * CH + c]; }
    int lane = blockIdx.x * 4 + threadIdx.y, nl = gridDim.x * 4;
    for (int e = lane; e < NE; e += nl) {
        int i = __ldg(&iInd[e]), j = __ldg(&jInd[e]);
        float s = 0.f;
#pragma unroll
        for (int l = 0; l < NLAYERS; l++) {
            const float* Y = g_Y4 + (size_t)l * NN * CH;
            float v = Y[i * CH + c] - Y[j * CH + c];
            s += fmaxf((v - mc[l]) * ic[l], 0.f);
        }
        g_EB[(size_t)e * 256 + 128 + c] = HSTEP * s;
    }
}

// ================= launch ====================================================
extern "C" void kernel_launch(void* const* d_in, const int* in_sizes, int n_in,
                              void* d_out, int out_size) {
    const float* xn      = (const float*)d_in[0];
    const float* xe      = (const float*)d_in[1];
    const int*   iInd    = (const int*)d_in[2];
    const int*   jInd    = (const int*)d_in[3];
    const float* KNopen  = (const float*)d_in[4];
    const float* KEopen  = (const float*)d_in[5];
    const float* KNclose = (const float*)d_in[6];
    const float* KN      = (const float*)d_in[8];
    const float* KE      = (const float*)d_in[9];
    float*       out     = (float*)d_out;
    (void)in_sizes; (void)n_in; (void)out_size;

    cudaFuncSetAttribute((const void*)gemm_open,
                         cudaFuncAttributeMaxDynamicSharedMemorySize, GEMM_SMEM);
    cudaFuncSetAttribute((const void*)mma_gemm<128, false, false>,
                         cudaFuncAttributeMaxDynamicSharedMemorySize, MMA_SMEM);
    cudaFuncSetAttribute((const void*)mma_gemm<128, false, true>,
                         cudaFuncAttributeMaxDynamicSharedMemorySize, MMA_SMEM);
    cudaFuncSetAttribute((const void*)mma_gemm<128, true, false>,
                         cudaFuncAttributeMaxDynamicSharedMemorySize, MMA_SMEM);
    cudaFuncSetAttribute((const void*)mma_gemm<256, true, false>,
                         cudaFuncAttributeMaxDynamicSharedMemorySize, MMA_SMEM);

    float *pXn, *pY4, *pDacc, *pDraw, *pT, *pWc, *pM4, *pI4, *pMN, *pIN, *pEB;
    cudaGetSymbolAddress((void**)&pXn,   g_Xn);
    cudaGetSymbolAddress((void**)&pY4,   g_Y4);
    cudaGetSymbolAddress((void**)&pDacc, g_Dacc);
    cudaGetSymbolAddress((void**)&pDraw, g_Draw);
    cudaGetSymbolAddress((void**)&pT,    g_T);
    cudaGetSymbolAddress((void**)&pWc,   g_Wc);
    cudaGetSymbolAddress((void**)&pM4,   g_mean4);
    cudaGetSymbolAddress((void**)&pI4,   g_inv4);
    cudaGetSymbolAddress((void**)&pMN,   g_meanN);
    cudaGetSymbolAddress((void**)&pIN,   g_invN);
    cudaGetSymbolAddress((void**)&pEB,   g_EB);

    const int gN = (NN + 127) / 128;   // 391
    const int gE = (NE + 127) / 128;   // 3907
    const dim3 t128x4(128, 4);

    // CSR + raw-edge preprocessing
    csr_zero<<<98, 512>>>();
    csr_count<<<592, 256>>>(iInd, jInd);
    csr_scan<<<1, 1024>>>();
    csr_fill<<<592, 256>>>(iInd, jInd);
    transpose_xe<<<dim3((NE + 31) / 32, 4), dim3(32, 8)>>>(xe);
    div_raw<<<(NN + 3) / 4, t128x4>>>();
    make_wc<<<128, 128>>>(KNclose, KEopen);

    // open node GEMM (CM input), then Dacc = KEopen @ div(xe_raw)
    gemm_open<<<gN, 256, GEMM_SMEM>>>(xn, KNopen, pXn, NN);
    mma_gemm<128, false, false><<<gN, 256, MMA_SMEM>>>(pDraw, KEopen, pDacc, NN);

    for (int l = 0; l < NLAYERS; l++) {
        float* Yl = pY4 + (size_t)l * NN * CH;
        mma_gemm<128, false, false><<<gN, 256, MMA_SMEM>>>(pXn, KN + l * CH * CH, Yl, NN);
        edge_stats<<<1184, t128x4>>>(iInd, jInd, Yl);
        stats_finalize<<<1, CH>>>((float)NE, pM4 + l * CH, pI4 + l * CH);
        div_relu<<<(NN + 3) / 4, t128x4>>>(iInd, jInd, Yl, pM4 + l * CH, pI4 + l * CH);
        mma_gemm<128, false, true><<<gN, 256, MMA_SMEM>>>(pDacc, KE + l * CH * CH, pT, NN);
        row_stats<<<592, t128x4>>>(pT, NN);
        stats_finalize<<<1, CH>>>((float)NN, pMN, pIN);
        node_apply<<<592, 256>>>();
    }

    // S_e into g_EB cols 128:256, then both closes
    build_S<<<1184, t128x4>>>(iInd, jInd);
    mma_gemm<128, true, false><<<gN, 256, MMA_SMEM>>>(pXn, KNclose, out, NN);
    mma_gemm<256, true, false><<<gE, 256, MMA_SMEM>>>(pEB, pWc, out + (size_t)NN * CH, NE);
}